// round 5
// baseline (speedup 1.0000x reference)
#include <cuda_runtime.h>

#define NB 8       // batch
#define NT 12      // time / feature-in dim
#define NN 20000   // nodes
#define NE 320000  // edges
#define NF 64      // gcn hidden
#define NBT (NB * NT)   // 96 floats per node row
#define CAP 64          // bucket capacity (Poisson(16); P(>64) ~ 1e-20)

#define TP_BLOCKS (NN / 16)        // 1250 transpose blocks (16 nodes each)
#define FILL_BLOCKS (NE / 256)     // 1250 fill blocks

// Scratch (__device__ globals; ~18 MB, L2-resident).
// g_cnt starts zeroed (static init) and is re-zeroed by k2 every call.
__device__ __align__(128) float g_xt[(size_t)NN * NBT];  // [n][b*12+t]
__device__ __align__(128) int2  g_bkt[(size_t)NN * CAP]; // {src, w-as-int}
__device__ int g_cnt[NN];

// ---------------------------------------------------------------------------
// kA: fused transpose + edge bucketing. Blocks [0,1250) transpose 16 nodes
// each (smem staged, pad-17 rows -> <=3-way read conflicts); blocks
// [1250,2500) bucket 256 edges each. Independent work, overlapped in one
// launch to hide both latencies.
// ---------------------------------------------------------------------------
__global__ void __launch_bounds__(256) kA(
        const float* __restrict__ x,
        const int* __restrict__ esrc, const int* __restrict__ edst,
        const float* __restrict__ ew) {
    __shared__ float s[96 * 17];
    int tid = threadIdx.x;

    if (blockIdx.x < TP_BLOCKS) {
        int n0 = blockIdx.x * 16;
        // load 96 bt-rows x 16 nodes, coalesced over n
#pragma unroll
        for (int k = 0; k < 6; ++k) {
            int i = tid + 256 * k;          // 0..1535
            int bt = i >> 4, nl = i & 15;
            s[bt * 17 + nl] = x[(size_t)bt * NN + n0 + nl];
        }
        __syncthreads();
        // store 384 contiguous float4 (16 node-rows x 24 f4)
        float4* dst = reinterpret_cast<float4*>(g_xt) + (size_t)n0 * 24;
        for (int i = tid; i < 384; i += 256) {
            int n = i / 24, q = i % 24, r = 4 * q;
            dst[i] = make_float4(s[(r + 0) * 17 + n], s[(r + 1) * 17 + n],
                                 s[(r + 2) * 17 + n], s[(r + 3) * 17 + n]);
        }
    } else {
        int e = (blockIdx.x - TP_BLOCKS) * 256 + tid;   // exact: < NE
        int d = edst[e];
        int pos = atomicAdd(&g_cnt[d], 1);
        if (pos < CAP)
            g_bkt[(size_t)d * CAP + pos] = make_int2(esrc[e], __float_as_int(ew[e]));
    }
}

// ---------------------------------------------------------------------------
// k2: fused gather + epilogue, one warp per node. Gather unrolled x4:
// padding slots carry {src=0, w=0} so no predication needed; 12 independent
// LDGs in flight per unrolled step. Resets g_cnt for the next call.
// ---------------------------------------------------------------------------
__global__ void __launch_bounds__(256) k2_fused(
        const int* __restrict__ esrc, const int* __restrict__ edst,
        const float* __restrict__ ew,
        const float* __restrict__ w_gcn, const float* __restrict__ b_gcn,
        const float* __restrict__ w_dense, const float* __restrict__ b_dense,
        float* __restrict__ out) {
    __shared__ float s_wg[NT * NF];        // [t][f]
    __shared__ float s_wd[NF * NT];        // [f][t]
    __shared__ float s_bg[NF];
    __shared__ float s_bd[NT];
    __shared__ float s_agg[8][NBT];
    __shared__ float s_g[8][NB][NF + 1];

    int tid = threadIdx.x;
    int w = tid >> 5, lane = tid & 31;

    for (int i = tid; i < NT * NF; i += 256) { s_wg[i] = w_gcn[i]; s_wd[i] = w_dense[i]; }
    if (tid < NF) s_bg[tid] = b_gcn[tid];
    if (tid < NT) s_bd[tid] = b_dense[tid];
    __syncthreads();

    int node = blockIdx.x * 8 + w;          // 2500*8 == NN
    int cnt = g_cnt[node];
    if (lane == 0) g_cnt[node] = 0;         // reset for next call

    float a0 = 0.f, a1 = 0.f, a2 = 0.f;
    if (cnt <= CAP) {
        const int2* bp = g_bkt + (size_t)node * CAP;
        for (int base = 0; base < cnt; base += 32) {
            int m = cnt - base; if (m > 32) m = 32;
            int2 slot = (lane < m) ? bp[base + lane] : make_int2(0, 0);
            int m4 = (m + 3) & ~3;
            for (int j = 0; j < m4; j += 4) {
                float wt[4];
                const float* p[4];
#pragma unroll
                for (int k = 0; k < 4; ++k) {
                    int   ss = __shfl_sync(0xffffffffu, slot.x, j + k);
                    wt[k]    = __int_as_float(__shfl_sync(0xffffffffu, slot.y, j + k));
                    p[k]     = g_xt + (size_t)ss * NBT;
                }
                float v0[4], v1[4], v2[4];
#pragma unroll
                for (int k = 0; k < 4; ++k) {
                    v0[k] = p[k][lane];
                    v1[k] = p[k][lane + 32];
                    v2[k] = p[k][lane + 64];
                }
#pragma unroll
                for (int k = 0; k < 4; ++k) {
                    a0 += wt[k] * v0[k];
                    a1 += wt[k] * v1[k];
                    a2 += wt[k] * v2[k];
                }
            }
        }
    } else {
        // Unconditional-correctness fallback (statistically unreachable).
        for (int e = 0; e < NE; ++e) {
            if (__ldg(edst + e) == node) {
                float wt = __ldg(ew + e);
                const float* p = g_xt + (size_t)__ldg(esrc + e) * NBT;
                a0 += wt * p[lane]; a1 += wt * p[lane + 32]; a2 += wt * p[lane + 64];
            }
        }
    }

    s_agg[w][lane] = a0; s_agg[w][lane + 32] = a1; s_agg[w][lane + 64] = a2;
    __syncwarp();

    // g[b][f] = relu(agg[b,:] @ w_gcn + bg)
#pragma unroll
    for (int i = 0; i < 16; ++i) {
        int idx = lane + 32 * i;
        int b = idx >> 6, f = idx & 63;
        float g = s_bg[f];
#pragma unroll
        for (int t = 0; t < NT; ++t)
            g += s_agg[w][b * NT + t] * s_wg[t * NF + f];
        s_g[w][b][f] = fmaxf(g, 0.f);
    }
    __syncwarp();

    // out[b,node,t] = relu(g[b,:] @ w_dense + bd)
#pragma unroll
    for (int j = 0; j < 3; ++j) {
        int idx = lane + 32 * j;
        int b = idx / NT, t = idx - b * NT;
        float o = s_bd[t];
#pragma unroll
        for (int f = 0; f < NF; ++f)
            o += s_g[w][b][f] * s_wd[f * NT + t];
        out[((size_t)b * NN + node) * NT + t] = fmaxf(o, 0.f);
    }
}

// ---------------------------------------------------------------------------
extern "C" void kernel_launch(void* const* d_in, const int* in_sizes, int n_in,
                              void* d_out, int out_size) {
    const float* x       = (const float*)d_in[0];
    const float* ew      = (const float*)d_in[1];
    const float* w_gcn   = (const float*)d_in[2];
    const float* b_gcn   = (const float*)d_in[3];
    const float* w_dense = (const float*)d_in[4];
    const float* b_dense = (const float*)d_in[5];
    const int*   esrc    = (const int*)d_in[6];
    const int*   edst    = (const int*)d_in[7];
    float* out = (float*)d_out;

    kA<<<TP_BLOCKS + FILL_BLOCKS, 256>>>(x, esrc, edst, ew);
    k2_fused<<<NN / 8, 256>>>(esrc, edst, ew, w_gcn, b_gcn, w_dense, b_dense, out);
}

// round 6
// speedup vs baseline: 1.1707x; 1.1707x over previous
#include <cuda_runtime.h>

#define NB 8       // batch
#define NT 12      // time / feature-in dim
#define NN 20000   // nodes
#define NE 320000  // edges
#define NF 64      // gcn hidden
#define NBT (NB * NT)   // 96 floats per node row
#define CAP 64          // bucket capacity (Poisson(16); P(>64) ~ 1e-20)

#define TP_BLOCKS (NN / 16)        // 1250 transpose blocks (16 nodes each)
#define FILL_BLOCKS (NE / 256)     // 1250 fill blocks (exact)

// Scratch (__device__ globals; ~25 MB, L2-resident).
// g_cnt starts zeroed (static init) and is re-zeroed by k2 every call.
__device__ __align__(128) float g_xt [(size_t)NN * NBT];  // [n][b*12+t]
__device__ __align__(128) float g_agg[(size_t)NN * NBT];  // [n][b*12+t]
__device__ __align__(128) int2  g_bkt[(size_t)NN * CAP];  // {src, w-as-int}
__device__ int g_cnt[NN];

// ---------------------------------------------------------------------------
// kA: fused transpose + edge bucketing (independent block ranges, overlapped).
// ---------------------------------------------------------------------------
__global__ void __launch_bounds__(256) kA(
        const float* __restrict__ x,
        const int* __restrict__ esrc, const int* __restrict__ edst,
        const float* __restrict__ ew) {
    __shared__ float s[96 * 17];
    int tid = threadIdx.x;

    if (blockIdx.x < TP_BLOCKS) {
        int n0 = blockIdx.x * 16;
#pragma unroll
        for (int k = 0; k < 6; ++k) {
            int i = tid + 256 * k;          // 0..1535
            int bt = i >> 4, nl = i & 15;
            s[bt * 17 + nl] = x[(size_t)bt * NN + n0 + nl];
        }
        __syncthreads();
        float4* dst = reinterpret_cast<float4*>(g_xt) + (size_t)n0 * 24;
        for (int i = tid; i < 384; i += 256) {
            int n = i / 24, q = i % 24, r = 4 * q;
            dst[i] = make_float4(s[(r + 0) * 17 + n], s[(r + 1) * 17 + n],
                                 s[(r + 2) * 17 + n], s[(r + 3) * 17 + n]);
        }
    } else {
        int e = (blockIdx.x - TP_BLOCKS) * 256 + tid;   // < NE exactly
        int d = edst[e];
        int pos = atomicAdd(&g_cnt[d], 1);
        if (pos < CAP)
            g_bkt[(size_t)d * CAP + pos] = make_int2(esrc[e], __float_as_int(ew[e]));
    }
}

// ---------------------------------------------------------------------------
// k2: PURE gather, one warp per node. Lanes 0-23 each own one float4 column
// of the 96-float row: per edge = 1 LDG.128 + 4 FMA (3 L2 lines, perfectly
// coalesced). Edge metadata broadcast via shfl, 4-edge unroll (scalar temps).
// Writes agg row with a single coalesced 384B float4 store. Resets g_cnt.
// ---------------------------------------------------------------------------
__global__ void __launch_bounds__(256) k2_gather(
        const int* __restrict__ esrc, const int* __restrict__ edst,
        const float* __restrict__ ew) {
    int tid = threadIdx.x;
    int w = tid >> 5, lane = tid & 31;
    int node = blockIdx.x * 8 + w;          // 2500*8 == NN
    int cnt = g_cnt[node];
    if (lane == 0) g_cnt[node] = 0;         // leave zeroed for next call

    float4 acc = make_float4(0.f, 0.f, 0.f, 0.f);
    const float4* xt4 = reinterpret_cast<const float4*>(g_xt);

    if (cnt <= CAP) {
        const int2* bp = g_bkt + (size_t)node * CAP;
        int2 sl0 = (lane      < cnt) ? bp[lane]      : make_int2(0, 0);
        int2 sl1 = (lane + 32 < cnt) ? bp[lane + 32] : make_int2(0, 0);

        int c1 = cnt < 32 ? cnt : 32;
        for (int j = 0; j < c1; j += 4) {   // padded slots have w=0 (harmless)
            int   s0 = __shfl_sync(~0u, sl0.x, j + 0);
            int   s1 = __shfl_sync(~0u, sl0.x, j + 1);
            int   s2 = __shfl_sync(~0u, sl0.x, j + 2);
            int   s3 = __shfl_sync(~0u, sl0.x, j + 3);
            float w0 = __int_as_float(__shfl_sync(~0u, sl0.y, j + 0));
            float w1 = __int_as_float(__shfl_sync(~0u, sl0.y, j + 1));
            float w2 = __int_as_float(__shfl_sync(~0u, sl0.y, j + 2));
            float w3 = __int_as_float(__shfl_sync(~0u, sl0.y, j + 3));
            if (lane < 24) {
                float4 v0 = xt4[(size_t)s0 * 24 + lane];
                float4 v1 = xt4[(size_t)s1 * 24 + lane];
                float4 v2 = xt4[(size_t)s2 * 24 + lane];
                float4 v3 = xt4[(size_t)s3 * 24 + lane];
                acc.x += w0 * v0.x; acc.y += w0 * v0.y; acc.z += w0 * v0.z; acc.w += w0 * v0.w;
                acc.x += w1 * v1.x; acc.y += w1 * v1.y; acc.z += w1 * v1.z; acc.w += w1 * v1.w;
                acc.x += w2 * v2.x; acc.y += w2 * v2.y; acc.z += w2 * v2.z; acc.w += w2 * v2.w;
                acc.x += w3 * v3.x; acc.y += w3 * v3.y; acc.z += w3 * v3.z; acc.w += w3 * v3.w;
            }
        }
        int c2 = cnt - 32;
        for (int j = 0; j < c2; j += 4) {
            int   s0 = __shfl_sync(~0u, sl1.x, j + 0);
            int   s1 = __shfl_sync(~0u, sl1.x, j + 1);
            int   s2 = __shfl_sync(~0u, sl1.x, j + 2);
            int   s3 = __shfl_sync(~0u, sl1.x, j + 3);
            float w0 = __int_as_float(__shfl_sync(~0u, sl1.y, j + 0));
            float w1 = __int_as_float(__shfl_sync(~0u, sl1.y, j + 1));
            float w2 = __int_as_float(__shfl_sync(~0u, sl1.y, j + 2));
            float w3 = __int_as_float(__shfl_sync(~0u, sl1.y, j + 3));
            if (lane < 24) {
                float4 v0 = xt4[(size_t)s0 * 24 + lane];
                float4 v1 = xt4[(size_t)s1 * 24 + lane];
                float4 v2 = xt4[(size_t)s2 * 24 + lane];
                float4 v3 = xt4[(size_t)s3 * 24 + lane];
                acc.x += w0 * v0.x; acc.y += w0 * v0.y; acc.z += w0 * v0.z; acc.w += w0 * v0.w;
                acc.x += w1 * v1.x; acc.y += w1 * v1.y; acc.z += w1 * v1.z; acc.w += w1 * v1.w;
                acc.x += w2 * v2.x; acc.y += w2 * v2.y; acc.z += w2 * v2.z; acc.w += w2 * v2.w;
                acc.x += w3 * v3.x; acc.y += w3 * v3.y; acc.z += w3 * v3.z; acc.w += w3 * v3.w;
            }
        }
    } else {
        // Unconditional-correctness fallback (statistically unreachable).
        for (int e = 0; e < NE; ++e) {
            if (__ldg(edst + e) == node) {
                float wt = __ldg(ew + e);
                if (lane < 24) {
                    float4 v = xt4[(size_t)__ldg(esrc + e) * 24 + lane];
                    acc.x += wt * v.x; acc.y += wt * v.y;
                    acc.z += wt * v.z; acc.w += wt * v.w;
                }
            }
        }
    }

    if (lane < 24)
        reinterpret_cast<float4*>(g_agg)[(size_t)node * 24 + lane] = acc;
}

// ---------------------------------------------------------------------------
// k3: epilogue, one thread per (b,n) with gid = n*8+b (dense agg reads).
// Weight indices are warp-uniform -> LDS broadcasts co-issue with FMA.
//   g[f]       = relu( sum_t agg * w_gcn[t,f] + bg[f] )
//   out[b,n,t] = relu( sum_f g[f] * w_dense[f,t] + bd[t] )
// ---------------------------------------------------------------------------
__global__ void __launch_bounds__(256) k3_out(
        const float* __restrict__ w_gcn, const float* __restrict__ b_gcn,
        const float* __restrict__ w_dense, const float* __restrict__ b_dense,
        float* __restrict__ out) {
    __shared__ float s_wg[NT * NF];   // [t][f]
    __shared__ float s_wd[NF * NT];   // [f][t]
    __shared__ float s_bg[NF];
    __shared__ float s_bd[NT];
    int tid = threadIdx.x;
    for (int i = tid; i < NT * NF; i += 256) { s_wg[i] = w_gcn[i]; s_wd[i] = w_dense[i]; }
    if (tid < NF) s_bg[tid] = b_gcn[tid];
    if (tid < NT) s_bd[tid] = b_dense[tid];
    __syncthreads();

    int gid = blockIdx.x * 256 + tid;     // n*8 + b, total 160000 (exact grid)
    int n = gid >> 3, b = gid & 7;

    float a[NT], o[NT];
    const float4* p = reinterpret_cast<const float4*>(g_agg + (size_t)n * NBT + b * NT);
#pragma unroll
    for (int q = 0; q < 3; ++q) {
        float4 v = p[q];
        a[4*q] = v.x; a[4*q+1] = v.y; a[4*q+2] = v.z; a[4*q+3] = v.w;
    }
#pragma unroll
    for (int t = 0; t < NT; ++t) o[t] = 0.f;

#pragma unroll 4
    for (int f = 0; f < NF; ++f) {
        float g = s_bg[f];
#pragma unroll
        for (int t = 0; t < NT; ++t) g += a[t] * s_wg[t * NF + f];
        g = fmaxf(g, 0.f);
#pragma unroll
        for (int t = 0; t < NT; ++t) o[t] += g * s_wd[f * NT + t];
    }

    float* op = out + ((size_t)b * NN + n) * NT;
#pragma unroll
    for (int t = 0; t < NT; ++t)
        op[t] = fmaxf(o[t] + s_bd[t], 0.f);
}

// ---------------------------------------------------------------------------
extern "C" void kernel_launch(void* const* d_in, const int* in_sizes, int n_in,
                              void* d_out, int out_size) {
    const float* x       = (const float*)d_in[0];
    const float* ew      = (const float*)d_in[1];
    const float* w_gcn   = (const float*)d_in[2];
    const float* b_gcn   = (const float*)d_in[3];
    const float* w_dense = (const float*)d_in[4];
    const float* b_dense = (const float*)d_in[5];
    const int*   esrc    = (const int*)d_in[6];
    const int*   edst    = (const int*)d_in[7];
    float* out = (float*)d_out;

    kA<<<TP_BLOCKS + FILL_BLOCKS, 256>>>(x, esrc, edst, ew);
    k2_gather<<<NN / 8, 256>>>(esrc, edst, ew);
    k3_out<<<(NB * NN) / 256, 256>>>(w_gcn, b_gcn, w_dense, b_dense, out);
}

// round 7
// speedup vs baseline: 1.2279x; 1.0488x over previous
#include <cuda_runtime.h>

#define NB 8       // batch
#define NT 12      // time / feature-in dim
#define NN 20000   // nodes
#define NE 320000  // edges
#define NF 64      // gcn hidden
#define NBT (NB * NT)   // 96 floats per node row
#define CAP 64          // bucket capacity (Poisson(16); P(>64) ~ 1e-20)

#define TP_BLOCKS (NN / 32)        // 625 transpose blocks (32 nodes each)
#define FILL_BLOCKS (NE / 256)     // 1250 fill blocks (exact)

// Scratch (__device__ globals; ~25 MB, L2-resident).
// g_cnt starts zeroed (static init) and is re-zeroed by k2 every call.
__device__ __align__(128) float g_xt [(size_t)NN * NBT];  // [n][b*12+t]
__device__ __align__(128) float g_agg[(size_t)NN * NBT];  // [n][b*12+t]
__device__ __align__(128) int2  g_bkt[(size_t)NN * CAP];  // {src, w-as-int}
__device__ int g_cnt[NN];

// ---- f32x2 packed helpers (Blackwell FFMA2 path) ---------------------------
__device__ __forceinline__ unsigned long long pk2(float lo, float hi) {
    unsigned long long r;
    asm("mov.b64 %0, {%1, %2};" : "=l"(r) : "f"(lo), "f"(hi));
    return r;
}
__device__ __forceinline__ void upk2(float& lo, float& hi, unsigned long long v) {
    asm("mov.b64 {%0, %1}, %2;" : "=f"(lo), "=f"(hi) : "l"(v));
}
#define FFMA2(d, a, b, c) \
    asm("fma.rn.f32x2 %0, %1, %2, %3;" : "=l"(d) : "l"(a), "l"(b), "l"(c))

// ---------------------------------------------------------------------------
// kA: fused transpose + edge bucketing. Transpose blocks: 32-node tiles,
// float4 loads AND stores (3 LDG.128 + 12 STS + 12 LDS + 3 STG.128 / thread).
// ---------------------------------------------------------------------------
__global__ void __launch_bounds__(256) kA(
        const float* __restrict__ x,
        const int* __restrict__ esrc, const int* __restrict__ edst,
        const float* __restrict__ ew) {
    __shared__ float s[96 * 33];    // [bt][n], pad 33 for conflict control
    int tid = threadIdx.x;

    if (blockIdx.x < TP_BLOCKS) {
        int n0 = blockIdx.x * 32;
        const float4* x4 = reinterpret_cast<const float4*>(x);
#pragma unroll
        for (int k = 0; k < 3; ++k) {
            int i = tid + 256 * k;          // 0..767
            int bt = i >> 3, q = i & 7;     // 8 float4 per 32-node row
            float4 v = x4[(size_t)bt * (NN / 4) + (n0 >> 2) + q];
            s[bt * 33 + 4 * q + 0] = v.x;
            s[bt * 33 + 4 * q + 1] = v.y;
            s[bt * 33 + 4 * q + 2] = v.z;
            s[bt * 33 + 4 * q + 3] = v.w;
        }
        __syncthreads();
        float4* dst = reinterpret_cast<float4*>(g_xt) + (size_t)n0 * 24;
#pragma unroll
        for (int k = 0; k < 3; ++k) {
            int o4 = tid + 256 * k;         // 0..767 contiguous float4 stores
            int n = o4 / 24, q = o4 % 24, r = 4 * q;
            dst[o4] = make_float4(s[(r + 0) * 33 + n], s[(r + 1) * 33 + n],
                                  s[(r + 2) * 33 + n], s[(r + 3) * 33 + n]);
        }
    } else {
        int e = (blockIdx.x - TP_BLOCKS) * 256 + tid;   // < NE exactly
        int d = edst[e];
        int pos = atomicAdd(&g_cnt[d], 1);
        if (pos < CAP)
            g_bkt[(size_t)d * CAP + pos] = make_int2(esrc[e], __float_as_int(ew[e]));
    }
}

// ---------------------------------------------------------------------------
// k2: pure gather, one warp per node (unchanged from R6). Resets g_cnt.
// ---------------------------------------------------------------------------
__global__ void __launch_bounds__(256) k2_gather(
        const int* __restrict__ esrc, const int* __restrict__ edst,
        const float* __restrict__ ew) {
    int tid = threadIdx.x;
    int w = tid >> 5, lane = tid & 31;
    int node = blockIdx.x * 8 + w;          // 2500*8 == NN
    int cnt = g_cnt[node];
    if (lane == 0) g_cnt[node] = 0;         // leave zeroed for next call

    float4 acc = make_float4(0.f, 0.f, 0.f, 0.f);
    const float4* xt4 = reinterpret_cast<const float4*>(g_xt);

    if (cnt <= CAP) {
        const int2* bp = g_bkt + (size_t)node * CAP;
        int2 sl0 = (lane      < cnt) ? bp[lane]      : make_int2(0, 0);
        int2 sl1 = (lane + 32 < cnt) ? bp[lane + 32] : make_int2(0, 0);

        int c1 = cnt < 32 ? cnt : 32;
        for (int j = 0; j < c1; j += 4) {   // padded slots carry w=0
            int   s0 = __shfl_sync(~0u, sl0.x, j + 0);
            int   s1 = __shfl_sync(~0u, sl0.x, j + 1);
            int   s2 = __shfl_sync(~0u, sl0.x, j + 2);
            int   s3 = __shfl_sync(~0u, sl0.x, j + 3);
            float w0 = __int_as_float(__shfl_sync(~0u, sl0.y, j + 0));
            float w1 = __int_as_float(__shfl_sync(~0u, sl0.y, j + 1));
            float w2 = __int_as_float(__shfl_sync(~0u, sl0.y, j + 2));
            float w3 = __int_as_float(__shfl_sync(~0u, sl0.y, j + 3));
            if (lane < 24) {
                float4 v0 = xt4[(size_t)s0 * 24 + lane];
                float4 v1 = xt4[(size_t)s1 * 24 + lane];
                float4 v2 = xt4[(size_t)s2 * 24 + lane];
                float4 v3 = xt4[(size_t)s3 * 24 + lane];
                acc.x += w0 * v0.x; acc.y += w0 * v0.y; acc.z += w0 * v0.z; acc.w += w0 * v0.w;
                acc.x += w1 * v1.x; acc.y += w1 * v1.y; acc.z += w1 * v1.z; acc.w += w1 * v1.w;
                acc.x += w2 * v2.x; acc.y += w2 * v2.y; acc.z += w2 * v2.z; acc.w += w2 * v2.w;
                acc.x += w3 * v3.x; acc.y += w3 * v3.y; acc.z += w3 * v3.z; acc.w += w3 * v3.w;
            }
        }
        int c2 = cnt - 32;
        for (int j = 0; j < c2; j += 4) {
            int   s0 = __shfl_sync(~0u, sl1.x, j + 0);
            int   s1 = __shfl_sync(~0u, sl1.x, j + 1);
            int   s2 = __shfl_sync(~0u, sl1.x, j + 2);
            int   s3 = __shfl_sync(~0u, sl1.x, j + 3);
            float w0 = __int_as_float(__shfl_sync(~0u, sl1.y, j + 0));
            float w1 = __int_as_float(__shfl_sync(~0u, sl1.y, j + 1));
            float w2 = __int_as_float(__shfl_sync(~0u, sl1.y, j + 2));
            float w3 = __int_as_float(__shfl_sync(~0u, sl1.y, j + 3));
            if (lane < 24) {
                float4 v0 = xt4[(size_t)s0 * 24 + lane];
                float4 v1 = xt4[(size_t)s1 * 24 + lane];
                float4 v2 = xt4[(size_t)s2 * 24 + lane];
                float4 v3 = xt4[(size_t)s3 * 24 + lane];
                acc.x += w0 * v0.x; acc.y += w0 * v0.y; acc.z += w0 * v0.z; acc.w += w0 * v0.w;
                acc.x += w1 * v1.x; acc.y += w1 * v1.y; acc.z += w1 * v1.z; acc.w += w1 * v1.w;
                acc.x += w2 * v2.x; acc.y += w2 * v2.y; acc.z += w2 * v2.z; acc.w += w2 * v2.w;
                acc.x += w3 * v3.x; acc.y += w3 * v3.y; acc.z += w3 * v3.z; acc.w += w3 * v3.w;
            }
        }
    } else {
        // Unconditional-correctness fallback (statistically unreachable).
        for (int e = 0; e < NE; ++e) {
            if (__ldg(edst + e) == node) {
                float wt = __ldg(ew + e);
                if (lane < 24) {
                    float4 v = xt4[(size_t)__ldg(esrc + e) * 24 + lane];
                    acc.x += wt * v.x; acc.y += wt * v.y;
                    acc.z += wt * v.z; acc.w += wt * v.w;
                }
            }
        }
    }

    if (lane < 24)
        reinterpret_cast<float4*>(g_agg)[(size_t)node * 24 + lane] = acc;
}

// ---------------------------------------------------------------------------
// k3: epilogue. One thread per (node, 4-batch group): each weight LDS feeds
// 4 uses, math in packed f32x2 (2 batch-pairs). 40000 threads total.
// ---------------------------------------------------------------------------
__global__ void __launch_bounds__(256) k3_out(
        const float* __restrict__ w_gcn, const float* __restrict__ b_gcn,
        const float* __restrict__ w_dense, const float* __restrict__ b_dense,
        float* __restrict__ out) {
    __shared__ float s_wg[NT * NF];   // [t][f]
    __shared__ float s_wd[NF * NT];   // [f][t]
    __shared__ float s_bg[NF];
    __shared__ float s_bd[NT];
    int tid = threadIdx.x;
    for (int i = tid; i < NT * NF; i += 256) { s_wg[i] = w_gcn[i]; s_wd[i] = w_dense[i]; }
    if (tid < NF) s_bg[tid] = b_gcn[tid];
    if (tid < NT) s_bd[tid] = b_dense[tid];
    __syncthreads();

    int gid = blockIdx.x * 256 + tid;     // (n, half): 40000 total
    if (gid >= NN * 2) return;
    int n = gid >> 1, half = gid & 1;     // batches b0 = 4*half .. +3

    // Load 48 floats (4 batch rows of 12) and pack into batch-pair f32x2:
    // A[p][t] = { a[b0+2p][t], a[b0+2p+1][t] }
    unsigned long long A[2][NT], O[2][NT];
    {
        const float4* p = reinterpret_cast<const float4*>(
            g_agg + (size_t)n * NBT + half * 48);
        float a[4][NT];
#pragma unroll
        for (int q = 0; q < 12; ++q) {
            float4 v = p[q];
            int b = q / 3, r = (q % 3) * 4;
            a[b][r + 0] = v.x; a[b][r + 1] = v.y; a[b][r + 2] = v.z; a[b][r + 3] = v.w;
        }
#pragma unroll
        for (int t = 0; t < NT; ++t) {
            A[0][t] = pk2(a[0][t], a[1][t]);
            A[1][t] = pk2(a[2][t], a[3][t]);
            O[0][t] = 0ull;
            O[1][t] = 0ull;
        }
    }

#pragma unroll 4
    for (int f = 0; f < NF; ++f) {
        float bgf = s_bg[f];
        unsigned long long G0 = pk2(bgf, bgf);
        unsigned long long G1 = G0;
#pragma unroll
        for (int t = 0; t < NT; ++t) {
            unsigned long long w2 = pk2(s_wg[t * NF + f], s_wg[t * NF + f]);
            FFMA2(G0, A[0][t], w2, G0);
            FFMA2(G1, A[1][t], w2, G1);
        }
        // relu both halves
        float g0l, g0h, g1l, g1h;
        upk2(g0l, g0h, G0); upk2(g1l, g1h, G1);
        G0 = pk2(fmaxf(g0l, 0.f), fmaxf(g0h, 0.f));
        G1 = pk2(fmaxf(g1l, 0.f), fmaxf(g1h, 0.f));
#pragma unroll
        for (int t = 0; t < NT; ++t) {
            unsigned long long w2 = pk2(s_wd[f * NT + t], s_wd[f * NT + t]);
            FFMA2(O[0][t], G0, w2, O[0][t]);
            FFMA2(O[1][t], G1, w2, O[1][t]);
        }
    }

    // Unpack, add bias, relu, store 4 batch rows (3 float4 each).
#pragma unroll
    for (int p = 0; p < 2; ++p) {
        float lo[NT], hi[NT];
#pragma unroll
        for (int t = 0; t < NT; ++t) {
            float l, h; upk2(l, h, O[p][t]);
            lo[t] = fmaxf(l + s_bd[t], 0.f);
            hi[t] = fmaxf(h + s_bd[t], 0.f);
        }
        int b_lo = half * 4 + 2 * p;
        float4* q0 = reinterpret_cast<float4*>(out + ((size_t)b_lo * NN + n) * NT);
        float4* q1 = reinterpret_cast<float4*>(out + ((size_t)(b_lo + 1) * NN + n) * NT);
#pragma unroll
        for (int q = 0; q < 3; ++q) {
            q0[q] = make_float4(lo[4*q], lo[4*q+1], lo[4*q+2], lo[4*q+3]);
            q1[q] = make_float4(hi[4*q], hi[4*q+1], hi[4*q+2], hi[4*q+3]);
        }
    }
}

// ---------------------------------------------------------------------------
extern "C" void kernel_launch(void* const* d_in, const int* in_sizes, int n_in,
                              void* d_out, int out_size) {
    const float* x       = (const float*)d_in[0];
    const float* ew      = (const float*)d_in[1];
    const float* w_gcn   = (const float*)d_in[2];
    const float* b_gcn   = (const float*)d_in[3];
    const float* w_dense = (const float*)d_in[4];
    const float* b_dense = (const float*)d_in[5];
    const int*   esrc    = (const int*)d_in[6];
    const int*   edst    = (const int*)d_in[7];
    float* out = (float*)d_out;

    kA<<<TP_BLOCKS + FILL_BLOCKS, 256>>>(x, esrc, edst, ew);
    k2_gather<<<NN / 8, 256>>>(esrc, edst, ew);
    k3_out<<<(NN * 2 + 255) / 256, 256>>>(w_gcn, b_gcn, w_dense, b_dense, out);
}

// round 8
// speedup vs baseline: 1.2741x; 1.0376x over previous
#include <cuda_runtime.h>

#define NB 8       // batch
#define NT 12      // time / feature-in dim
#define NN 20000   // nodes
#define NE 320000  // edges
#define NF 64      // gcn hidden
#define NBT (NB * NT)   // 96 floats per node row
#define CAP 64          // bucket capacity (Poisson(16); P(>64) ~ 1e-20)

#define TP_BLOCKS (NN / 32)        // 625 transpose blocks (32 nodes each)
#define FILL_BLOCKS (NE / 256)     // 1250 fill blocks (exact)

// Scratch (__device__ globals; ~25 MB, L2-resident).
// g_cnt starts zeroed (static init) and is re-zeroed by k2 every call.
__device__ __align__(128) float g_xt [(size_t)NN * NBT];  // [n][b*12+t]
__device__ __align__(128) float g_agg[(size_t)NN * NBT];  // [n][b*12+t]
__device__ __align__(128) int2  g_bkt[(size_t)NN * CAP];  // {src, w-as-int}
__device__ int g_cnt[NN];

// ---- f32x2 packed helpers ---------------------------------------------------
__device__ __forceinline__ unsigned long long pk2(float lo, float hi) {
    unsigned long long r;
    asm("mov.b64 %0, {%1, %2};" : "=l"(r) : "f"(lo), "f"(hi));
    return r;
}
__device__ __forceinline__ void upk2(float& lo, float& hi, unsigned long long v) {
    asm("mov.b64 {%0, %1}, %2;" : "=f"(lo), "=f"(hi) : "l"(v));
}
#define FFMA2(d, a, b, c) \
    asm("fma.rn.f32x2 %0, %1, %2, %3;" : "=l"(d) : "l"(a), "l"(b), "l"(c))

// ---------------------------------------------------------------------------
// kA: fused transpose + edge bucketing (unchanged from R7).
// ---------------------------------------------------------------------------
__global__ void __launch_bounds__(256) kA(
        const float* __restrict__ x,
        const int* __restrict__ esrc, const int* __restrict__ edst,
        const float* __restrict__ ew) {
    __shared__ float s[96 * 33];
    int tid = threadIdx.x;

    if (blockIdx.x < TP_BLOCKS) {
        int n0 = blockIdx.x * 32;
        const float4* x4 = reinterpret_cast<const float4*>(x);
#pragma unroll
        for (int k = 0; k < 3; ++k) {
            int i = tid + 256 * k;
            int bt = i >> 3, q = i & 7;
            float4 v = x4[(size_t)bt * (NN / 4) + (n0 >> 2) + q];
            s[bt * 33 + 4 * q + 0] = v.x;
            s[bt * 33 + 4 * q + 1] = v.y;
            s[bt * 33 + 4 * q + 2] = v.z;
            s[bt * 33 + 4 * q + 3] = v.w;
        }
        __syncthreads();
        float4* dst = reinterpret_cast<float4*>(g_xt) + (size_t)n0 * 24;
#pragma unroll
        for (int k = 0; k < 3; ++k) {
            int o4 = tid + 256 * k;
            int n = o4 / 24, q = o4 % 24, r = 4 * q;
            dst[o4] = make_float4(s[(r + 0) * 33 + n], s[(r + 1) * 33 + n],
                                  s[(r + 2) * 33 + n], s[(r + 3) * 33 + n]);
        }
    } else {
        int e = (blockIdx.x - TP_BLOCKS) * 256 + tid;
        int d = edst[e];
        int pos = atomicAdd(&g_cnt[d], 1);
        if (pos < CAP)
            g_bkt[(size_t)d * CAP + pos] = make_int2(esrc[e], __float_as_int(ew[e]));
    }
}

// ---------------------------------------------------------------------------
// k2: pure gather, one warp per node (unchanged from R6/R7). Resets g_cnt.
// ---------------------------------------------------------------------------
__global__ void __launch_bounds__(256) k2_gather(
        const int* __restrict__ esrc, const int* __restrict__ edst,
        const float* __restrict__ ew) {
    int tid = threadIdx.x;
    int w = tid >> 5, lane = tid & 31;
    int node = blockIdx.x * 8 + w;
    int cnt = g_cnt[node];
    if (lane == 0) g_cnt[node] = 0;

    float4 acc = make_float4(0.f, 0.f, 0.f, 0.f);
    const float4* xt4 = reinterpret_cast<const float4*>(g_xt);

    if (cnt <= CAP) {
        const int2* bp = g_bkt + (size_t)node * CAP;
        int2 sl0 = (lane      < cnt) ? bp[lane]      : make_int2(0, 0);
        int2 sl1 = (lane + 32 < cnt) ? bp[lane + 32] : make_int2(0, 0);

        int c1 = cnt < 32 ? cnt : 32;
        for (int j = 0; j < c1; j += 4) {
            int   s0 = __shfl_sync(~0u, sl0.x, j + 0);
            int   s1 = __shfl_sync(~0u, sl0.x, j + 1);
            int   s2 = __shfl_sync(~0u, sl0.x, j + 2);
            int   s3 = __shfl_sync(~0u, sl0.x, j + 3);
            float w0 = __int_as_float(__shfl_sync(~0u, sl0.y, j + 0));
            float w1 = __int_as_float(__shfl_sync(~0u, sl0.y, j + 1));
            float w2 = __int_as_float(__shfl_sync(~0u, sl0.y, j + 2));
            float w3 = __int_as_float(__shfl_sync(~0u, sl0.y, j + 3));
            if (lane < 24) {
                float4 v0 = xt4[(size_t)s0 * 24 + lane];
                float4 v1 = xt4[(size_t)s1 * 24 + lane];
                float4 v2 = xt4[(size_t)s2 * 24 + lane];
                float4 v3 = xt4[(size_t)s3 * 24 + lane];
                acc.x += w0 * v0.x; acc.y += w0 * v0.y; acc.z += w0 * v0.z; acc.w += w0 * v0.w;
                acc.x += w1 * v1.x; acc.y += w1 * v1.y; acc.z += w1 * v1.z; acc.w += w1 * v1.w;
                acc.x += w2 * v2.x; acc.y += w2 * v2.y; acc.z += w2 * v2.z; acc.w += w2 * v2.w;
                acc.x += w3 * v3.x; acc.y += w3 * v3.y; acc.z += w3 * v3.z; acc.w += w3 * v3.w;
            }
        }
        int c2 = cnt - 32;
        for (int j = 0; j < c2; j += 4) {
            int   s0 = __shfl_sync(~0u, sl1.x, j + 0);
            int   s1 = __shfl_sync(~0u, sl1.x, j + 1);
            int   s2 = __shfl_sync(~0u, sl1.x, j + 2);
            int   s3 = __shfl_sync(~0u, sl1.x, j + 3);
            float w0 = __int_as_float(__shfl_sync(~0u, sl1.y, j + 0));
            float w1 = __int_as_float(__shfl_sync(~0u, sl1.y, j + 1));
            float w2 = __int_as_float(__shfl_sync(~0u, sl1.y, j + 2));
            float w3 = __int_as_float(__shfl_sync(~0u, sl1.y, j + 3));
            if (lane < 24) {
                float4 v0 = xt4[(size_t)s0 * 24 + lane];
                float4 v1 = xt4[(size_t)s1 * 24 + lane];
                float4 v2 = xt4[(size_t)s2 * 24 + lane];
                float4 v3 = xt4[(size_t)s3 * 24 + lane];
                acc.x += w0 * v0.x; acc.y += w0 * v0.y; acc.z += w0 * v0.z; acc.w += w0 * v0.w;
                acc.x += w1 * v1.x; acc.y += w1 * v1.y; acc.z += w1 * v1.z; acc.w += w1 * v1.w;
                acc.x += w2 * v2.x; acc.y += w2 * v2.y; acc.z += w2 * v2.z; acc.w += w2 * v2.w;
                acc.x += w3 * v3.x; acc.y += w3 * v3.y; acc.z += w3 * v3.z; acc.w += w3 * v3.w;
            }
        }
    } else {
        // Unconditional-correctness fallback (statistically unreachable).
        for (int e = 0; e < NE; ++e) {
            if (__ldg(edst + e) == node) {
                float wt = __ldg(ew + e);
                if (lane < 24) {
                    float4 v = xt4[(size_t)__ldg(esrc + e) * 24 + lane];
                    acc.x += wt * v.x; acc.y += wt * v.y;
                    acc.z += wt * v.z; acc.w += wt * v.w;
                }
            }
        }
    }

    if (lane < 24)
        reinterpret_cast<float4*>(g_agg)[(size_t)node * 24 + lane] = acc;
}

// ---------------------------------------------------------------------------
// k3: epilogue, one thread per (node, 4-batch half). 128-thread blocks ->
// 313 blocks (>=2/SM). Weights pre-duplicated in smem as float2 {w,w}: inner
// loop is bare LDS.64 + FFMA2, each weight load feeds 2 batch-pairs.
// ---------------------------------------------------------------------------
__global__ void __launch_bounds__(128) k3_out(
        const float* __restrict__ w_gcn, const float* __restrict__ b_gcn,
        const float* __restrict__ w_dense, const float* __restrict__ b_dense,
        float* __restrict__ out) {
    __shared__ float2 s_wg2[NT * NF];   // [t][f] duplicated
    __shared__ float2 s_wd2[NF * NT];   // [f][t] duplicated
    __shared__ float2 s_bg2[NF];
    __shared__ float  s_bd[NT];
    int tid = threadIdx.x;
    for (int i = tid; i < NT * NF; i += 128) {
        float a = w_gcn[i];   s_wg2[i] = make_float2(a, a);
        float b = w_dense[i]; s_wd2[i] = make_float2(b, b);
    }
    if (tid < NF) { float v = b_gcn[tid]; s_bg2[tid] = make_float2(v, v); }
    if (tid < NT) s_bd[tid] = b_dense[tid];
    __syncthreads();

    int gid = blockIdx.x * 128 + tid;     // (n, half): 40000 total
    if (gid >= NN * 2) return;
    int n = gid >> 1, half = gid & 1;     // batches b0 = 4*half .. +3

    // A[p][t] = { agg[b0+2p][t], agg[b0+2p+1][t] }
    unsigned long long A[2][NT], O[2][NT];
    {
        const float4* p = reinterpret_cast<const float4*>(
            g_agg + (size_t)n * NBT + half * 48);
        float a[4][NT];
#pragma unroll
        for (int q = 0; q < 12; ++q) {
            float4 v = p[q];
            int b = q / 3, r = (q % 3) * 4;
            a[b][r + 0] = v.x; a[b][r + 1] = v.y; a[b][r + 2] = v.z; a[b][r + 3] = v.w;
        }
#pragma unroll
        for (int t = 0; t < NT; ++t) {
            A[0][t] = pk2(a[0][t], a[1][t]);
            A[1][t] = pk2(a[2][t], a[3][t]);
            O[0][t] = 0ull;
            O[1][t] = 0ull;
        }
    }

    const unsigned long long* wg2 = reinterpret_cast<const unsigned long long*>(s_wg2);
    const unsigned long long* wd2 = reinterpret_cast<const unsigned long long*>(s_wd2);
    const unsigned long long* bg2 = reinterpret_cast<const unsigned long long*>(s_bg2);

#pragma unroll 4
    for (int f = 0; f < NF; ++f) {
        unsigned long long G0 = bg2[f];
        unsigned long long G1 = G0;
#pragma unroll
        for (int t = 0; t < NT; ++t) {
            unsigned long long w2 = wg2[t * NF + f];
            FFMA2(G0, A[0][t], w2, G0);
            FFMA2(G1, A[1][t], w2, G1);
        }
        float g0l, g0h, g1l, g1h;
        upk2(g0l, g0h, G0); upk2(g1l, g1h, G1);
        G0 = pk2(fmaxf(g0l, 0.f), fmaxf(g0h, 0.f));
        G1 = pk2(fmaxf(g1l, 0.f), fmaxf(g1h, 0.f));
#pragma unroll
        for (int t = 0; t < NT; ++t) {
            unsigned long long w2 = wd2[f * NT + t];
            FFMA2(O[0][t], G0, w2, O[0][t]);
            FFMA2(O[1][t], G1, w2, O[1][t]);
        }
    }

#pragma unroll
    for (int p = 0; p < 2; ++p) {
        float lo[NT], hi[NT];
#pragma unroll
        for (int t = 0; t < NT; ++t) {
            float l, h; upk2(l, h, O[p][t]);
            lo[t] = fmaxf(l + s_bd[t], 0.f);
            hi[t] = fmaxf(h + s_bd[t], 0.f);
        }
        int b_lo = half * 4 + 2 * p;
        float4* q0 = reinterpret_cast<float4*>(out + ((size_t)b_lo * NN + n) * NT);
        float4* q1 = reinterpret_cast<float4*>(out + ((size_t)(b_lo + 1) * NN + n) * NT);
#pragma unroll
        for (int q = 0; q < 3; ++q) {
            q0[q] = make_float4(lo[4*q], lo[4*q+1], lo[4*q+2], lo[4*q+3]);
            q1[q] = make_float4(hi[4*q], hi[4*q+1], hi[4*q+2], hi[4*q+3]);
        }
    }
}

// ---------------------------------------------------------------------------
extern "C" void kernel_launch(void* const* d_in, const int* in_sizes, int n_in,
                              void* d_out, int out_size) {
    const float* x       = (const float*)d_in[0];
    const float* ew      = (const float*)d_in[1];
    const float* w_gcn   = (const float*)d_in[2];
    const float* b_gcn   = (const float*)d_in[3];
    const float* w_dense = (const float*)d_in[4];
    const float* b_dense = (const float*)d_in[5];
    const int*   esrc    = (const int*)d_in[6];
    const int*   edst    = (const int*)d_in[7];
    float* out = (float*)d_out;

    kA<<<TP_BLOCKS + FILL_BLOCKS, 256>>>(x, esrc, edst, ew);
    k2_gather<<<NN / 8, 256>>>(esrc, edst, ew);
    k3_out<<<(NN * 2 + 127) / 128, 128>>>(w_gcn, b_gcn, w_dense, b_dense, out);
}

// round 9
// speedup vs baseline: 1.4103x; 1.1068x over previous
#include <cuda_runtime.h>
#include <cuda_fp16.h>

#define NB 8       // batch
#define NT 12      // time / feature-in dim
#define NN 20000   // nodes
#define NE 320000  // edges
#define NF 64      // gcn hidden
#define NBT (NB * NT)   // 96 values per node row
#define CAP 64          // bucket capacity (Poisson(16); P(>64) ~ 1e-20)

#define TP_BLOCKS (NN / 32)        // 625 transpose blocks (32 nodes each)
#define FILL_BLOCKS (NE / 256)     // 1250 fill blocks (exact)

// Scratch (__device__ globals; ~21 MB, L2-resident).
// g_cnt starts zeroed (static init) and is re-zeroed by k2 every call.
__device__ __align__(128) uint2 g_xth[(size_t)NN * 24];   // fp16 xt: [n][96 halves]
__device__ __align__(128) float g_agg[(size_t)NN * NBT];  // fp32 [n][b*12+t]
__device__ __align__(128) int2  g_bkt[(size_t)NN * CAP];  // {src, w-as-int}
__device__ int g_cnt[NN];

// ---- f32x2 packed helpers ---------------------------------------------------
__device__ __forceinline__ unsigned long long pk2(float lo, float hi) {
    unsigned long long r;
    asm("mov.b64 %0, {%1, %2};" : "=l"(r) : "f"(lo), "f"(hi));
    return r;
}
__device__ __forceinline__ void upk2(float& lo, float& hi, unsigned long long v) {
    asm("mov.b64 {%0, %1}, %2;" : "=f"(lo), "=f"(hi) : "l"(v));
}
#define FFMA2(d, a, b, c) \
    asm("fma.rn.f32x2 %0, %1, %2, %3;" : "=l"(d) : "l"(a), "l"(b), "l"(c))

__device__ __forceinline__ uint2 pack4h(float a, float b, float c, float d) {
    __half2 lo = __floats2half2_rn(a, b);
    __half2 hi = __floats2half2_rn(c, d);
    uint2 r;
    r.x = *reinterpret_cast<unsigned*>(&lo);
    r.y = *reinterpret_cast<unsigned*>(&hi);
    return r;
}

// ---------------------------------------------------------------------------
// kA: fused transpose(+fp16 convert) + edge bucketing.
// ---------------------------------------------------------------------------
__global__ void __launch_bounds__(256) kA(
        const float* __restrict__ x,
        const int* __restrict__ esrc, const int* __restrict__ edst,
        const float* __restrict__ ew) {
    __shared__ float s[96 * 33];
    int tid = threadIdx.x;

    if (blockIdx.x < TP_BLOCKS) {
        int n0 = blockIdx.x * 32;
        const float4* x4 = reinterpret_cast<const float4*>(x);
#pragma unroll
        for (int k = 0; k < 3; ++k) {
            int i = tid + 256 * k;
            int bt = i >> 3, q = i & 7;
            float4 v = x4[(size_t)bt * (NN / 4) + (n0 >> 2) + q];
            s[bt * 33 + 4 * q + 0] = v.x;
            s[bt * 33 + 4 * q + 1] = v.y;
            s[bt * 33 + 4 * q + 2] = v.z;
            s[bt * 33 + 4 * q + 3] = v.w;
        }
        __syncthreads();
        uint2* dst = g_xth + (size_t)n0 * 24;
#pragma unroll
        for (int k = 0; k < 3; ++k) {
            int o2 = tid + 256 * k;         // 0..767 contiguous 8B stores
            int n = o2 / 24, q = o2 % 24, r = 4 * q;
            dst[o2] = pack4h(s[(r + 0) * 33 + n], s[(r + 1) * 33 + n],
                             s[(r + 2) * 33 + n], s[(r + 3) * 33 + n]);
        }
    } else {
        int e = (blockIdx.x - TP_BLOCKS) * 256 + tid;
        int d = edst[e];
        int pos = atomicAdd(&g_cnt[d], 1);
        if (pos < CAP)
            g_bkt[(size_t)d * CAP + pos] = make_int2(esrc[e], __float_as_int(ew[e]));
    }
}

// ---------------------------------------------------------------------------
// k2: pure gather, one warp per node. Per edge: 1 LDG.64 of 4 fp16 (lane<24),
// cvt to fp32, 4 FFMA. Rows are 192B = 2 L2 lines (was 384B/3 lines).
// fp32 accumulate; writes fp32 agg row (coalesced float4). Resets g_cnt.
// ---------------------------------------------------------------------------
__global__ void __launch_bounds__(256) k2_gather(
        const int* __restrict__ esrc, const int* __restrict__ edst,
        const float* __restrict__ ew) {
    int tid = threadIdx.x;
    int w = tid >> 5, lane = tid & 31;
    int node = blockIdx.x * 8 + w;
    int cnt = g_cnt[node];
    if (lane == 0) g_cnt[node] = 0;

    float4 acc = make_float4(0.f, 0.f, 0.f, 0.f);

    if (cnt <= CAP) {
        const int2* bp = g_bkt + (size_t)node * CAP;
        int2 sl0 = (lane      < cnt) ? bp[lane]      : make_int2(0, 0);
        int2 sl1 = (lane + 32 < cnt) ? bp[lane + 32] : make_int2(0, 0);

        int c1 = cnt < 32 ? cnt : 32;
        for (int j = 0; j < c1; j += 4) {   // padded slots carry w=0
            int   s0 = __shfl_sync(~0u, sl0.x, j + 0);
            int   s1 = __shfl_sync(~0u, sl0.x, j + 1);
            int   s2 = __shfl_sync(~0u, sl0.x, j + 2);
            int   s3 = __shfl_sync(~0u, sl0.x, j + 3);
            float w0 = __int_as_float(__shfl_sync(~0u, sl0.y, j + 0));
            float w1 = __int_as_float(__shfl_sync(~0u, sl0.y, j + 1));
            float w2 = __int_as_float(__shfl_sync(~0u, sl0.y, j + 2));
            float w3 = __int_as_float(__shfl_sync(~0u, sl0.y, j + 3));
            if (lane < 24) {
                uint2 u0 = g_xth[(size_t)s0 * 24 + lane];
                uint2 u1 = g_xth[(size_t)s1 * 24 + lane];
                uint2 u2 = g_xth[(size_t)s2 * 24 + lane];
                uint2 u3 = g_xth[(size_t)s3 * 24 + lane];
                float2 a, b;
                a = __half22float2(*reinterpret_cast<__half2*>(&u0.x));
                b = __half22float2(*reinterpret_cast<__half2*>(&u0.y));
                acc.x += w0 * a.x; acc.y += w0 * a.y; acc.z += w0 * b.x; acc.w += w0 * b.y;
                a = __half22float2(*reinterpret_cast<__half2*>(&u1.x));
                b = __half22float2(*reinterpret_cast<__half2*>(&u1.y));
                acc.x += w1 * a.x; acc.y += w1 * a.y; acc.z += w1 * b.x; acc.w += w1 * b.y;
                a = __half22float2(*reinterpret_cast<__half2*>(&u2.x));
                b = __half22float2(*reinterpret_cast<__half2*>(&u2.y));
                acc.x += w2 * a.x; acc.y += w2 * a.y; acc.z += w2 * b.x; acc.w += w2 * b.y;
                a = __half22float2(*reinterpret_cast<__half2*>(&u3.x));
                b = __half22float2(*reinterpret_cast<__half2*>(&u3.y));
                acc.x += w3 * a.x; acc.y += w3 * a.y; acc.z += w3 * b.x; acc.w += w3 * b.y;
            }
        }
        int c2 = cnt - 32;
        for (int j = 0; j < c2; j += 4) {
            int   s0 = __shfl_sync(~0u, sl1.x, j + 0);
            int   s1 = __shfl_sync(~0u, sl1.x, j + 1);
            int   s2 = __shfl_sync(~0u, sl1.x, j + 2);
            int   s3 = __shfl_sync(~0u, sl1.x, j + 3);
            float w0 = __int_as_float(__shfl_sync(~0u, sl1.y, j + 0));
            float w1 = __int_as_float(__shfl_sync(~0u, sl1.y, j + 1));
            float w2 = __int_as_float(__shfl_sync(~0u, sl1.y, j + 2));
            float w3 = __int_as_float(__shfl_sync(~0u, sl1.y, j + 3));
            if (lane < 24) {
                uint2 u0 = g_xth[(size_t)s0 * 24 + lane];
                uint2 u1 = g_xth[(size_t)s1 * 24 + lane];
                uint2 u2 = g_xth[(size_t)s2 * 24 + lane];
                uint2 u3 = g_xth[(size_t)s3 * 24 + lane];
                float2 a, b;
                a = __half22float2(*reinterpret_cast<__half2*>(&u0.x));
                b = __half22float2(*reinterpret_cast<__half2*>(&u0.y));
                acc.x += w0 * a.x; acc.y += w0 * a.y; acc.z += w0 * b.x; acc.w += w0 * b.y;
                a = __half22float2(*reinterpret_cast<__half2*>(&u1.x));
                b = __half22float2(*reinterpret_cast<__half2*>(&u1.y));
                acc.x += w1 * a.x; acc.y += w1 * a.y; acc.z += w1 * b.x; acc.w += w1 * b.y;
                a = __half22float2(*reinterpret_cast<__half2*>(&u2.x));
                b = __half22float2(*reinterpret_cast<__half2*>(&u2.y));
                acc.x += w2 * a.x; acc.y += w2 * a.y; acc.z += w2 * b.x; acc.w += w2 * b.y;
                a = __half22float2(*reinterpret_cast<__half2*>(&u3.x));
                b = __half22float2(*reinterpret_cast<__half2*>(&u3.y));
                acc.x += w3 * a.x; acc.y += w3 * a.y; acc.z += w3 * b.x; acc.w += w3 * b.y;
            }
        }
    } else {
        // Unconditional-correctness fallback (statistically unreachable).
        for (int e = 0; e < NE; ++e) {
            if (__ldg(edst + e) == node) {
                float wt = __ldg(ew + e);
                if (lane < 24) {
                    uint2 u = g_xth[(size_t)__ldg(esrc + e) * 24 + lane];
                    float2 a = __half22float2(*reinterpret_cast<__half2*>(&u.x));
                    float2 b = __half22float2(*reinterpret_cast<__half2*>(&u.y));
                    acc.x += wt * a.x; acc.y += wt * a.y;
                    acc.z += wt * b.x; acc.w += wt * b.y;
                }
            }
        }
    }

    if (lane < 24)
        reinterpret_cast<float4*>(g_agg)[(size_t)node * 24 + lane] = acc;
}

// ---------------------------------------------------------------------------
// k3: epilogue (unchanged from R8). One thread per (node, 4-batch half);
// weights pre-duplicated in smem as float2 {w,w}; LDS.64 + FFMA2 inner loop.
// ---------------------------------------------------------------------------
__global__ void __launch_bounds__(128) k3_out(
        const float* __restrict__ w_gcn, const float* __restrict__ b_gcn,
        const float* __restrict__ w_dense, const float* __restrict__ b_dense,
        float* __restrict__ out) {
    __shared__ float2 s_wg2[NT * NF];   // [t][f] duplicated
    __shared__ float2 s_wd2[NF * NT];   // [f][t] duplicated
    __shared__ float2 s_bg2[NF];
    __shared__ float  s_bd[NT];
    int tid = threadIdx.x;
    for (int i = tid; i < NT * NF; i += 128) {
        float a = w_gcn[i];   s_wg2[i] = make_float2(a, a);
        float b = w_dense[i]; s_wd2[i] = make_float2(b, b);
    }
    if (tid < NF) { float v = b_gcn[tid]; s_bg2[tid] = make_float2(v, v); }
    if (tid < NT) s_bd[tid] = b_dense[tid];
    __syncthreads();

    int gid = blockIdx.x * 128 + tid;     // (n, half): 40000 total
    if (gid >= NN * 2) return;
    int n = gid >> 1, half = gid & 1;     // batches b0 = 4*half .. +3

    unsigned long long A[2][NT], O[2][NT];
    {
        const float4* p = reinterpret_cast<const float4*>(
            g_agg + (size_t)n * NBT + half * 48);
        float a[4][NT];
#pragma unroll
        for (int q = 0; q < 12; ++q) {
            float4 v = p[q];
            int b = q / 3, r = (q % 3) * 4;
            a[b][r + 0] = v.x; a[b][r + 1] = v.y; a[b][r + 2] = v.z; a[b][r + 3] = v.w;
        }
#pragma unroll
        for (int t = 0; t < NT; ++t) {
            A[0][t] = pk2(a[0][t], a[1][t]);
            A[1][t] = pk2(a[2][t], a[3][t]);
            O[0][t] = 0ull;
            O[1][t] = 0ull;
        }
    }

    const unsigned long long* wg2 = reinterpret_cast<const unsigned long long*>(s_wg2);
    const unsigned long long* wd2 = reinterpret_cast<const unsigned long long*>(s_wd2);
    const unsigned long long* bg2 = reinterpret_cast<const unsigned long long*>(s_bg2);

#pragma unroll 4
    for (int f = 0; f < NF; ++f) {
        unsigned long long G0 = bg2[f];
        unsigned long long G1 = G0;
#pragma unroll
        for (int t = 0; t < NT; ++t) {
            unsigned long long w2 = wg2[t * NF + f];
            FFMA2(G0, A[0][t], w2, G0);
            FFMA2(G1, A[1][t], w2, G1);
        }
        float g0l, g0h, g1l, g1h;
        upk2(g0l, g0h, G0); upk2(g1l, g1h, G1);
        G0 = pk2(fmaxf(g0l, 0.f), fmaxf(g0h, 0.f));
        G1 = pk2(fmaxf(g1l, 0.f), fmaxf(g1h, 0.f));
#pragma unroll
        for (int t = 0; t < NT; ++t) {
            unsigned long long w2 = wd2[f * NT + t];
            FFMA2(O[0][t], G0, w2, O[0][t]);
            FFMA2(O[1][t], G1, w2, O[1][t]);
        }
    }

#pragma unroll
    for (int p = 0; p < 2; ++p) {
        float lo[NT], hi[NT];
#pragma unroll
        for (int t = 0; t < NT; ++t) {
            float l, h; upk2(l, h, O[p][t]);
            lo[t] = fmaxf(l + s_bd[t], 0.f);
            hi[t] = fmaxf(h + s_bd[t], 0.f);
        }
        int b_lo = half * 4 + 2 * p;
        float4* q0 = reinterpret_cast<float4*>(out + ((size_t)b_lo * NN + n) * NT);
        float4* q1 = reinterpret_cast<float4*>(out + ((size_t)(b_lo + 1) * NN + n) * NT);
#pragma unroll
        for (int q = 0; q < 3; ++q) {
            q0[q] = make_float4(lo[4*q], lo[4*q+1], lo[4*q+2], lo[4*q+3]);
            q1[q] = make_float4(hi[4*q], hi[4*q+1], hi[4*q+2], hi[4*q+3]);
        }
    }
}

// ---------------------------------------------------------------------------
extern "C" void kernel_launch(void* const* d_in, const int* in_sizes, int n_in,
                              void* d_out, int out_size) {
    const float* x       = (const float*)d_in[0];
    const float* ew      = (const float*)d_in[1];
    const float* w_gcn   = (const float*)d_in[2];
    const float* b_gcn   = (const float*)d_in[3];
    const float* w_dense = (const float*)d_in[4];
    const float* b_dense = (const float*)d_in[5];
    const int*   esrc    = (const int*)d_in[6];
    const int*   edst    = (const int*)d_in[7];
    float* out = (float*)d_out;

    kA<<<TP_BLOCKS + FILL_BLOCKS, 256>>>(x, esrc, edst, ew);
    k2_gather<<<NN / 8, 256>>>(esrc, edst, ew);
    k3_out<<<(NN * 2 + 127) / 128, 128>>>(w_gcn, b_gcn, w_dense, b_dense, out);
}